// round 11
// baseline (speedup 1.0000x reference)
#include <cuda_runtime.h>
#include <math.h>

#define BATCH 8
#define VDIM 5000
#define CDIM 256
#define KDIM 200
#define PB   40             // panel width
#define NPAN (KDIM/PB)      // 5
#define NSYS (BATCH*KDIM)   // 1600
#define MROW 204            // padded row stride of M
#define PROW 168            // padded row stride of P^T (max T = 160)

// Scratch (device globals)
__device__ float g_Ap[3][BATCH*KDIM*CDIM];
__device__ float g_Bp[3][BATCH*KDIM*CDIM];
__device__ float g_A [BATCH*KDIM*CDIM];
__device__ float g_Bc[BATCH*KDIM*CDIM];
__device__ float g_S [BATCH*KDIM*KDIM];
__device__ float g_R [BATCH*KDIM*KDIM];
__device__ float g_M   [(size_t)NSYS*KDIM*MROW];
__device__ float g_P   [(size_t)NSYS*PB*PROW];
__device__ float g_RHS [NSYS*KDIM];
__device__ float g_DINV[NSYS*KDIM];
__device__ float g_DSH [NSYS*KDIM];

__device__ __constant__ int c_vstart[3] = {0, 1672, 3344};
__device__ __constant__ int c_vlen[3]   = {1672, 1672, 1656};

// ---------------------------------------------------------------------------
// Kernel 1: partial A[b,k,c] over a V chunk. grid (4,4,48)
// ---------------------------------------------------------------------------
__global__ __launch_bounds__(256) void k_gemm_feat(
    const float* __restrict__ fx, const float* __restrict__ fy,
    const float* __restrict__ ex, const float* __restrict__ ey)
{
    const int bz    = blockIdx.z;
    const int b     = bz & 7;
    const int which = (bz >> 3) & 1;
    const int vs    = bz >> 4;
    const float* E = (which ? ey : ex) + (size_t)b*KDIM*VDIM;
    const float* F = (which ? fy : fx) + (size_t)b*VDIM*CDIM;
    float*       C = (which ? g_Bp[vs] : g_Ap[vs]) + (size_t)b*KDIM*CDIM;

    const int vbeg = c_vstart[vs];
    const int vend = vbeg + c_vlen[vs];

    const int m0 = blockIdx.y * 64;
    const int n0 = blockIdx.x * 64;

    __shared__ float As[2][8][64];
    __shared__ float Bs[2][8][64];

    const int tid = threadIdx.x;
    const int tx  = tid & 15;
    const int ty  = tid >> 4;

    const bool isA = tid < 128;
    const int  t2  = tid & 127;
    const int  lrow = t2 >> 1;
    const int  lv4  = (t2 & 1) * 4;
    const int  fvr  = t2 >> 4;
    const int  fc4  = (t2 & 15) * 4;
    const bool arow_ok = (m0 + lrow < KDIM);

    float acc[4][4];
    #pragma unroll
    for (int i = 0; i < 4; ++i)
        #pragma unroll
        for (int j = 0; j < 4; ++j) acc[i][j] = 0.f;

    {
        float4 pre = make_float4(0.f,0.f,0.f,0.f);
        if (isA) {
            if (arow_ok)
                pre = *reinterpret_cast<const float4*>(E + (size_t)(m0 + lrow)*VDIM + vbeg + lv4);
            As[0][lv4+0][lrow] = pre.x; As[0][lv4+1][lrow] = pre.y;
            As[0][lv4+2][lrow] = pre.z; As[0][lv4+3][lrow] = pre.w;
        } else {
            pre = *reinterpret_cast<const float4*>(F + (size_t)(vbeg + fvr)*CDIM + n0 + fc4);
            *reinterpret_cast<float4*>(&Bs[0][fvr][fc4]) = pre;
        }
    }
    __syncthreads();

    int buf = 0;
    for (int v0 = vbeg; v0 < vend; v0 += 8) {
        const int vn = v0 + 8;
        const bool has = vn < vend;
        float4 nxt = make_float4(0.f,0.f,0.f,0.f);
        if (has) {
            if (isA) {
                if (arow_ok)
                    nxt = *reinterpret_cast<const float4*>(E + (size_t)(m0 + lrow)*VDIM + vn + lv4);
            } else {
                nxt = *reinterpret_cast<const float4*>(F + (size_t)(vn + fvr)*CDIM + n0 + fc4);
            }
        }

        #pragma unroll
        for (int kk = 0; kk < 8; ++kk) {
            float4 a  = *reinterpret_cast<const float4*>(&As[buf][kk][ty*4]);
            float4 bb = *reinterpret_cast<const float4*>(&Bs[buf][kk][tx*4]);
            float am[4] = {a.x,a.y,a.z,a.w};
            float bn[4] = {bb.x,bb.y,bb.z,bb.w};
            #pragma unroll
            for (int i2 = 0; i2 < 4; ++i2)
                #pragma unroll
                for (int j2 = 0; j2 < 4; ++j2)
                    acc[i2][j2] = fmaf(am[i2], bn[j2], acc[i2][j2]);
        }

        if (has) {
            const int nb = buf ^ 1;
            if (isA) {
                As[nb][lv4+0][lrow] = nxt.x; As[nb][lv4+1][lrow] = nxt.y;
                As[nb][lv4+2][lrow] = nxt.z; As[nb][lv4+3][lrow] = nxt.w;
            } else {
                *reinterpret_cast<float4*>(&Bs[nb][fvr][fc4]) = nxt;
            }
        }
        __syncthreads();
        buf ^= 1;
    }

    #pragma unroll
    for (int i2 = 0; i2 < 4; ++i2) {
        int k = m0 + ty*4 + i2;
        if (k < KDIM) {
            float4 v = make_float4(acc[i2][0], acc[i2][1], acc[i2][2], acc[i2][3]);
            *reinterpret_cast<float4*>(C + (size_t)k*CDIM + n0 + tx*4) = v;
        }
    }
}

__global__ __launch_bounds__(256) void k_reduce()
{
    const int id = blockIdx.x * 256 + threadIdx.x;
    const int NF4 = BATCH*KDIM*CDIM/4;
    const bool isA = id < NF4;
    const int j = isA ? id : id - NF4;
    const float4* p0 = reinterpret_cast<const float4*>(isA ? g_Ap[0] : g_Bp[0]);
    const float4* p1 = reinterpret_cast<const float4*>(isA ? g_Ap[1] : g_Bp[1]);
    const float4* p2 = reinterpret_cast<const float4*>(isA ? g_Ap[2] : g_Bp[2]);
    float4 a = p0[j], bq = p1[j], c = p2[j];
    float4 r = make_float4(a.x+bq.x+c.x, a.y+bq.y+c.y, a.z+bq.z+c.z, a.w+bq.w+c.w);
    reinterpret_cast<float4*>(isA ? g_A : g_Bc)[j] = r;
}

// ---------------------------------------------------------------------------
// Kernel 2: S[b] = A A^T, R[b] = Bc A^T
// ---------------------------------------------------------------------------
__global__ __launch_bounds__(256) void k_gemm_gram()
{
    const int bz    = blockIdx.z;
    const int b     = bz & 7;
    const int which = bz >> 3;
    const float* X = (which ? g_Bc : g_A) + (size_t)b*KDIM*CDIM;
    const float* Y = g_A + (size_t)b*KDIM*CDIM;
    float*       C = (which ? g_R : g_S) + (size_t)b*KDIM*KDIM;

    const int m0 = blockIdx.y * 64;
    const int n0 = blockIdx.x * 64;

    __shared__ float As[16][64];
    __shared__ float Bs[16][64];

    const int tid = threadIdx.x;
    const int tx  = tid & 15;
    const int ty  = tid >> 4;
    const int lr  = tid >> 2;
    const int lc4 = (tid & 3) * 4;

    float acc[4][4];
    #pragma unroll
    for (int i = 0; i < 4; ++i)
        #pragma unroll
        for (int j = 0; j < 4; ++j) acc[i][j] = 0.f;

    for (int c0 = 0; c0 < CDIM; c0 += 16) {
        float4 xa = make_float4(0.f,0.f,0.f,0.f), yb = make_float4(0.f,0.f,0.f,0.f);
        if (m0 + lr < KDIM) xa = *reinterpret_cast<const float4*>(X + (size_t)(m0+lr)*CDIM + c0 + lc4);
        if (n0 + lr < KDIM) yb = *reinterpret_cast<const float4*>(Y + (size_t)(n0+lr)*CDIM + c0 + lc4);
        __syncthreads();
        As[lc4+0][lr] = xa.x; As[lc4+1][lr] = xa.y; As[lc4+2][lr] = xa.z; As[lc4+3][lr] = xa.w;
        Bs[lc4+0][lr] = yb.x; Bs[lc4+1][lr] = yb.y; Bs[lc4+2][lr] = yb.z; Bs[lc4+3][lr] = yb.w;
        __syncthreads();
        #pragma unroll
        for (int kk = 0; kk < 16; ++kk) {
            float4 a  = *reinterpret_cast<const float4*>(&As[kk][ty*4]);
            float4 bb = *reinterpret_cast<const float4*>(&Bs[kk][tx*4]);
            float am[4] = {a.x,a.y,a.z,a.w}, bn[4] = {bb.x,bb.y,bb.z,bb.w};
            #pragma unroll
            for (int i2 = 0; i2 < 4; ++i2)
                #pragma unroll
                for (int j2 = 0; j2 < 4; ++j2)
                    acc[i2][j2] = fmaf(am[i2], bn[j2], acc[i2][j2]);
        }
    }

    for (int i2 = 0; i2 < 4; ++i2) {
        int k = m0 + ty*4 + i2;
        if (k >= KDIM) continue;
        for (int j2 = 0; j2 < 4; ++j2) {
            int l = n0 + tx*4 + j2;
            if (l >= KDIM) continue;
            C[(size_t)k*KDIM + l] = acc[i2][j2];
        }
    }
}

// ---------------------------------------------------------------------------
// k_prep: scaling, gamma/lambda, diag shifts, rhs copy. grid (KDIM, BATCH)
// ---------------------------------------------------------------------------
__global__ __launch_bounds__(256) void k_prep(
    const float* __restrict__ evx_all, const float* __restrict__ evy_all,
    const float* __restrict__ p_gamma, const float* __restrict__ p_lambda)
{
    __shared__ float red[8];
    const int irow = blockIdx.x;
    const int b    = blockIdx.y;
    const int sys  = b*KDIM + irow;
    const int tid  = threadIdx.x;
    const int lane = tid & 31;
    const int wid  = tid >> 5;

    const float* evx = evx_all + b*KDIM;
    const float* evy = evy_all + b*KDIM;

    const float graw  = p_gamma[0];
    const float lraw  = p_lambda[0];
    const float gamma = 1.f / (1.f + expf(-graw));
    const float sp    = fmaxf(lraw, 0.f) + log1pf(expf(-fabsf(lraw)));
    float lmbda = 10.f + sp * (1000.f - 10.f) / 1000.f;
    lmbda = fminf(fmaxf(lmbda, 10.f), 1000.f);

    float mv = 0.f;
    for (int j = tid; j < KDIM; j += 256) mv = fmaxf(mv, fmaxf(evx[j], evy[j]));
    #pragma unroll
    for (int o = 16; o > 0; o >>= 1) mv = fmaxf(mv, __shfl_xor_sync(0xffffffffu, mv, o));
    if (lane == 0) red[wid] = mv;
    __syncthreads();
    if (tid == 0) {
        float m2 = red[0];
        for (int w = 1; w < 8; ++w) m2 = fmaxf(m2, red[w]);
        red[0] = m2;
    }
    __syncthreads();
    const float scaling = red[0];

    const float gx = powf(evx[irow] / scaling, gamma);
    const float dx = 1.f / (gx*gx + 1.f);

    for (int k = tid; k < KDIM; k += 256) {
        float gy  = powf(evy[k] / scaling, gamma);
        float dy  = 1.f / (gy*gy + 1.f);
        float mre = gy*dy - gx*dx;
        float mim = dy - dx;
        g_DSH[sys*KDIM + k] = lmbda * (mre*mre + mim*mim);
        g_RHS[sys*KDIM + k] = g_R[((size_t)b*KDIM + irow)*KDIM + k];
    }
}

// ---------------------------------------------------------------------------
// k_panel<P>: 40x40 diag factor (2x 20-step shfl) + fwd-solve + panel TRSM.
// grid (NSYS), 256 threads.
// ---------------------------------------------------------------------------
template<int P>
__global__ __launch_bounds__(256) void k_panel()
{
    constexpr int K0   = P*PB;
    constexpr int KEND = K0 + PB;
    constexpr int T    = KDIM - KEND;
    const unsigned FM = 0x000FFFFFu;

    __shared__ float Dblk[PB][PB+1];
    __shared__ float dinv_s[PB];
    __shared__ float ys0[20];

    const int sys = blockIdx.x;
    const int b   = sys / KDIM;
    const int tid = threadIdx.x;
    const int lane = tid & 31;
    const int wid  = tid >> 5;

    const float* Sb = g_S + (size_t)b*KDIM*KDIM;
    float* M = g_M + (size_t)sys*KDIM*MROW;

    // load diag block (lower 40x40)
    for (int idx = tid; idx < PB*PB; idx += 256) {
        int r = idx / PB, c = idx - r*PB;
        if (c <= r) {
            float v;
            if (P == 0) {
                v = Sb[(K0 + r)*KDIM + K0 + c];
                if (c == r) v += g_DSH[sys*KDIM + K0 + r];
            } else {
                v = M[(size_t)(K0 + r)*MROW + K0 + c];
            }
            Dblk[r][c] = v;
        }
    }
    __syncthreads();

    if (wid == 0 && lane < 20) {
        // --- factor D00 ---
        {
            float a[20];
            #pragma unroll
            for (int m = 0; m < 20; ++m) a[m] = (m <= lane) ? Dblk[lane][m] : 0.f;
            float myinv = 0.f;
            #pragma unroll
            for (int kk = 0; kk < 20; ++kk) {
                float dval = __shfl_sync(FM, a[kk], kk);
                float inv  = rsqrtf(dval);
                if (lane == kk) { a[kk] = dval * inv; myinv = inv; }
                if (lane >  kk) a[kk] *= inv;
                #pragma unroll
                for (int m = kk + 1; m < 20; ++m) {
                    float Lmk = __shfl_sync(FM, a[kk], m);
                    if (lane >= m) a[m] = fmaf(-a[kk], Lmk, a[m]);
                }
            }
            #pragma unroll
            for (int m = 0; m < 20; ++m) if (m <= lane) Dblk[lane][m] = a[m];
            dinv_s[lane] = myinv;
        }
        __syncwarp(FM);
        // --- TRSM D10 (row 20+lane vs D00) ---
        float rowr[20];
        {
            #pragma unroll
            for (int m = 0; m < 20; ++m) rowr[m] = Dblk[20+lane][m];
            #pragma unroll
            for (int j = 0; j < 20; ++j) {
                float s = rowr[j];
                #pragma unroll
                for (int m = 0; m < j; ++m) s = fmaf(-rowr[m], Dblk[j][m], s);
                rowr[j] = s * dinv_s[j];
            }
            #pragma unroll
            for (int m = 0; m < 20; ++m) Dblk[20+lane][m] = rowr[m];
        }
        __syncwarp(FM);
        // --- syrk update of D11 (row 20+lane, cols 20..20+lane) ---
        for (int c = 0; c <= lane; ++c) {
            float s = Dblk[20+lane][20+c];
            #pragma unroll
            for (int m = 0; m < 20; ++m) s = fmaf(-rowr[m], Dblk[20+c][m], s);
            Dblk[20+lane][20+c] = s;
        }
        __syncwarp(FM);
        // --- factor D11 ---
        {
            float a[20];
            #pragma unroll
            for (int m = 0; m < 20; ++m) a[m] = (m <= lane) ? Dblk[20+lane][20+m] : 0.f;
            float myinv = 0.f;
            #pragma unroll
            for (int kk = 0; kk < 20; ++kk) {
                float dval = __shfl_sync(FM, a[kk], kk);
                float inv  = rsqrtf(dval);
                if (lane == kk) { a[kk] = dval * inv; myinv = inv; }
                if (lane >  kk) a[kk] *= inv;
                #pragma unroll
                for (int m = kk + 1; m < 20; ++m) {
                    float Lmk = __shfl_sync(FM, a[kk], m);
                    if (lane >= m) a[m] = fmaf(-a[kk], Lmk, a[m]);
                }
            }
            #pragma unroll
            for (int m = 0; m < 20; ++m) if (m <= lane) Dblk[20+lane][20+m] = a[m];
            dinv_s[20+lane] = myinv;
        }
        __syncwarp(FM);
        // --- write factored diag + dinv to global ---
        for (int m = 0; m <= lane; ++m)
            M[(size_t)(K0 + lane)*MROW + K0 + m] = Dblk[lane][m];
        #pragma unroll
        for (int m = 0; m < 20; ++m)
            M[(size_t)(K0 + 20 + lane)*MROW + K0 + m] = Dblk[20+lane][m];
        for (int m = 0; m <= lane; ++m)
            M[(size_t)(K0 + 20 + lane)*MROW + K0 + 20 + m] = Dblk[20+lane][20+m];
        g_DINV[sys*KDIM + K0 + lane]      = dinv_s[lane];
        g_DINV[sys*KDIM + K0 + 20 + lane] = dinv_s[20+lane];
        __syncwarp(FM);
        // --- forward solve y0, y1 ---
        {
            float r = g_RHS[sys*KDIM + K0 + lane];
            #pragma unroll
            for (int m = 0; m < 20; ++m) {
                float ym = __shfl_sync(FM, r, m) * dinv_s[m];
                if (lane == m) r = ym;
                if (lane >  m) r = fmaf(-Dblk[lane][m], ym, r);
            }
            ys0[lane] = r;
        }
        __syncwarp(FM);
        {
            float r1 = g_RHS[sys*KDIM + K0 + 20 + lane];
            #pragma unroll
            for (int m = 0; m < 20; ++m) r1 = fmaf(-Dblk[20+lane][m], ys0[m], r1);
            #pragma unroll
            for (int m = 0; m < 20; ++m) {
                float ym = __shfl_sync(FM, r1, m) * dinv_s[20+m];
                if (lane == m) r1 = ym;
                if (lane >  m) r1 = fmaf(-Dblk[20+lane][20+m], ym, r1);
            }
            g_RHS[sys*KDIM + K0 + lane]      = ys0[lane];
            g_RHS[sys*KDIM + K0 + 20 + lane] = r1;
        }
    }
    __syncthreads();

    // panel TRSM: T rows, one per thread
    if constexpr (T > 0) {
        if (tid < T) {
            const int i = KEND + tid;
            float row[PB];
            if (P == 0) {
                #pragma unroll
                for (int m = 0; m < PB; ++m) row[m] = Sb[(size_t)i*KDIM + K0 + m];
            } else {
                #pragma unroll
                for (int m = 0; m < PB; ++m) row[m] = M[(size_t)i*MROW + K0 + m];
            }
            #pragma unroll
            for (int j = 0; j < PB; ++j) {
                float s = row[j];
                #pragma unroll
                for (int m = 0; m < j; ++m) s = fmaf(-row[m], Dblk[j][m], s);
                row[j] = s * dinv_s[j];
            }
            #pragma unroll
            for (int m = 0; m < PB; ++m) {
                M[(size_t)i*MROW + K0 + m] = row[m];
                g_P[(size_t)sys*PB*PROW + m*PROW + tid] = row[m];
            }
        }
    }
}

// ---------------------------------------------------------------------------
// k_trail<P>: batched rank-40 trailing update (64x64 tiles) + rhs update.
// grid (NTILES+1, NSYS), 256 threads.
// ---------------------------------------------------------------------------
template<int P>
__global__ __launch_bounds__(256) void k_trail()
{
    constexpr int K0   = P*PB;
    constexpr int KEND = K0 + PB;
    constexpr int T    = KDIM - KEND;
    constexpr int NT64 = (T + 63) / 64;
    constexpr int NTILES = NT64*(NT64+1)/2;

    const int sys = blockIdx.y;
    const int tid = threadIdx.x;
    const float* Pp = g_P + (size_t)sys*PB*PROW;

    if ((int)blockIdx.x == NTILES) {
        __shared__ float ys[PB];
        if (tid < PB) ys[tid] = g_RHS[sys*KDIM + K0 + tid];
        __syncthreads();
        for (int r = tid; r < T; r += 256) {
            float s = g_RHS[sys*KDIM + KEND + r];
            #pragma unroll
            for (int m = 0; m < PB; ++m) s = fmaf(-Pp[m*PROW + r], ys[m], s);
            g_RHS[sys*KDIM + KEND + r] = s;
        }
        return;
    }

    int rem = blockIdx.x, ri = 0;
    while (rem > ri) { rem -= ri + 1; ++ri; }
    const int cj = rem;

    __shared__ float As[PB][68];
    __shared__ float Bs[PB][68];
    for (int idx = tid; idx < PB*64; idx += 256) {
        int k = idx >> 6, rr = idx & 63;
        int ra = 64*ri + rr;
        int rb = 64*cj + rr;
        As[k][rr] = (ra < T) ? Pp[k*PROW + ra] : 0.f;
        Bs[k][rr] = (rb < T) ? Pp[k*PROW + rb] : 0.f;
    }
    __syncthreads();

    const int tx = tid & 15;
    const int ty = tid >> 4;

    float acc[4][4];
    #pragma unroll
    for (int i2 = 0; i2 < 4; ++i2)
        #pragma unroll
        for (int j2 = 0; j2 < 4; ++j2) acc[i2][j2] = 0.f;

    #pragma unroll
    for (int k = 0; k < PB; ++k) {
        float4 av = *reinterpret_cast<const float4*>(&As[k][4*ty]);
        float4 bv = *reinterpret_cast<const float4*>(&Bs[k][4*tx]);
        float am[4] = {av.x,av.y,av.z,av.w};
        float bn[4] = {bv.x,bv.y,bv.z,bv.w};
        #pragma unroll
        for (int i2 = 0; i2 < 4; ++i2)
            #pragma unroll
            for (int j2 = 0; j2 < 4; ++j2)
                acc[i2][j2] = fmaf(am[i2], bn[j2], acc[i2][j2]);
    }

    float* M = g_M + (size_t)sys*KDIM*MROW;
    const int b = sys / KDIM;
    const float* Sb = g_S + (size_t)b*KDIM*KDIM;

    #pragma unroll
    for (int i2 = 0; i2 < 4; ++i2) {
        const int rr = 64*ri + 4*ty + i2;
        if (rr >= T) continue;
        const int i = KEND + rr;
        const int ccb = 64*cj + 4*tx;
        if (ccb + 3 < rr) {
            float4 v;
            if (P == 0) v = *reinterpret_cast<const float4*>(&Sb[(size_t)i*KDIM + KEND + ccb]);
            else        v = *reinterpret_cast<const float4*>(&M[(size_t)i*MROW + KEND + ccb]);
            v.x -= acc[i2][0]; v.y -= acc[i2][1];
            v.z -= acc[i2][2]; v.w -= acc[i2][3];
            *reinterpret_cast<float4*>(&M[(size_t)i*MROW + KEND + ccb]) = v;
        } else if (ccb <= rr) {
            #pragma unroll
            for (int q = 0; q < 4; ++q) {
                const int c = ccb + q;
                if (c > rr) break;
                float v;
                if (P == 0) {
                    v = Sb[(size_t)i*KDIM + KEND + c];
                    if (c == rr) v += g_DSH[sys*KDIM + i];
                } else {
                    v = M[(size_t)i*MROW + KEND + c];
                }
                M[(size_t)i*MROW + KEND + c] = v - acc[i2][q];
            }
        }
    }
}

// ---------------------------------------------------------------------------
// k_backall: full backward substitution, one CTA per system. 256 threads.
// ---------------------------------------------------------------------------
__global__ __launch_bounds__(256) void k_backall()
{
    const unsigned FM = 0x000FFFFFu;
    __shared__ float Dblk[PB][PB+1];
    __shared__ float xs[PB];

    const int sys = blockIdx.x;
    const int tid = threadIdx.x;
    const int lane = tid & 31;
    const int wid  = tid >> 5;
    const float* M = g_M + (size_t)sys*KDIM*MROW;

    for (int blk = NPAN - 1; blk >= 0; --blk) {
        const int BK0 = blk * PB;

        // stage diag block lower 40x40
        for (int idx = tid; idx < PB*PB; idx += 256) {
            int r = idx / PB, c = idx - r*PB;
            if (c <= r) Dblk[r][c] = M[(size_t)(BK0 + r)*MROW + BK0 + c];
        }
        __syncthreads();

        if (wid == 0 && lane < 20) {
            // x1: L11^T x1 = y1
            {
                float dv = g_DINV[sys*KDIM + BK0 + 20 + lane];
                float r  = g_RHS[sys*KDIM + BK0 + 20 + lane];
                #pragma unroll
                for (int m = 19; m >= 0; --m) {
                    float xm = __shfl_sync(FM, r, m) * __shfl_sync(FM, dv, m);
                    if (lane == m) r = xm;
                    if (lane <  m) r = fmaf(-Dblk[20+m][20+lane], xm, r);
                }
                xs[20+lane] = r;
                g_RHS[sys*KDIM + BK0 + 20 + lane] = r;
            }
            __syncwarp(FM);
            // x0: L00^T x0 = y0 - L10^T x1
            {
                float dv = g_DINV[sys*KDIM + BK0 + lane];
                float r  = g_RHS[sys*KDIM + BK0 + lane];
                #pragma unroll
                for (int m = 0; m < 20; ++m) r = fmaf(-Dblk[20+m][lane], xs[20+m], r);
                #pragma unroll
                for (int m = 19; m >= 0; --m) {
                    float xm = __shfl_sync(FM, r, m) * __shfl_sync(FM, dv, m);
                    if (lane == m) r = xm;
                    if (lane <  m) r = fmaf(-Dblk[m][lane], xm, r);
                }
                xs[lane] = r;
                g_RHS[sys*KDIM + BK0 + lane] = r;
            }
        }
        __syncthreads();

        // bulk: rows above the block
        for (int i = tid; i < BK0; i += 256) {
            float s = g_RHS[sys*KDIM + i];
            #pragma unroll
            for (int m = 0; m < PB; ++m)
                s = fmaf(-M[(size_t)(BK0 + m)*MROW + i], xs[m], s);
            g_RHS[sys*KDIM + i] = s;
        }
        __syncthreads();
    }
}

__global__ __launch_bounds__(256) void k_out(float* __restrict__ out)
{
    const int sys = blockIdx.x;
    for (int j = threadIdx.x; j < KDIM; j += 256)
        out[(size_t)sys*KDIM + j] = g_RHS[sys*KDIM + j];
}

// ---------------------------------------------------------------------------
extern "C" void kernel_launch(void* const* d_in, const int* in_sizes, int n_in,
                              void* d_out, int out_size)
{
    const float* feat_x  = (const float*)d_in[0];
    const float* feat_y  = (const float*)d_in[1];
    const float* evals_x = (const float*)d_in[2];
    const float* evals_y = (const float*)d_in[3];
    const float* evtx    = (const float*)d_in[4];
    const float* evty    = (const float*)d_in[5];
    const float* graw    = (const float*)d_in[6];
    const float* lraw    = (const float*)d_in[7];
    float* out = (float*)d_out;

    k_gemm_feat<<<dim3(4, 4, 48), 256>>>(feat_x, feat_y, evtx, evty);
    k_reduce<<<800, 256>>>();
    k_gemm_gram<<<dim3(4, 4, 16), 256>>>();
    k_prep<<<dim3(KDIM, BATCH), 256>>>(evals_x, evals_y, graw, lraw);

    k_panel<0><<<NSYS, 256>>>();  k_trail<0><<<dim3(7, NSYS), 256>>>();
    k_panel<1><<<NSYS, 256>>>();  k_trail<1><<<dim3(4, NSYS), 256>>>();
    k_panel<2><<<NSYS, 256>>>();  k_trail<2><<<dim3(4, NSYS), 256>>>();
    k_panel<3><<<NSYS, 256>>>();  k_trail<3><<<dim3(2, NSYS), 256>>>();
    k_panel<4><<<NSYS, 256>>>();

    k_backall<<<NSYS, 256>>>();
    k_out<<<NSYS, 256>>>(out);
}